// round 17
// baseline (speedup 1.0000x reference)
#include <cuda_runtime.h>
#include <cuda_fp16.h>
#include <cstdint>

// ============================================================
// Problem constants
// ============================================================
#define MDIM 32768
#define KDIM 1024
#define NDIM 1024

static constexpr int BM = 128;
static constexpr int BN = 256;
static constexpr int BKE = 32;             // K elements (fp16) per stage = 64 B rows
static constexpr int STAGES = 4;
static constexpr int KITERS = KDIM / BKE;  // 32
static constexpr int THREADS = 256;

// padded smem rows: 64 data bytes padded to 80 (16B aligned; conflict-free for
// ldmatrix: 8-row x 16B phase covers all 32 banks exactly once)
static constexpr int ROWB = 80;
static constexpr int A_STG = BM * ROWB;            // 10240
static constexpr int B_STG = BN * ROWB;            // 20480
static constexpr int STAGE_BYTES = A_STG + B_STG;  // 30720
static constexpr int SM_ALPHA = 0;                 // 256 floats
static constexpr int SM_BETA  = 1024;              // 256 floats
static constexpr int SM_TILES = 2048;
static constexpr int SMEM_TOTAL = SM_TILES + STAGES * STAGE_BYTES;  // 124928

static constexpr float EPSV = 1.1920928955078125e-07f;  // np.finfo(float32).eps

// ============================================================
// Device scratch (no allocations allowed)
// ============================================================
__device__ __align__(1024) __half g_wth[(size_t)NDIM * KDIM];   // 2 MB transposed weight [N,K]
__device__ float g_pmin[2048];
__device__ float g_pmax[2048];
__device__ int   g_w_mode;   // 0 = int8 storage, 1 = int32 storage, 2 = float32 storage

// ============================================================
// PTX helpers (baseline ISA only — harness targets compute_103, no tcgen05/TMA)
// ============================================================
__device__ __forceinline__ uint32_t smem_u32(const void* p) {
    uint32_t a;
    asm("{ .reg .u64 t; cvta.to.shared.u64 t, %1; cvt.u32.u64 %0, t; }"
        : "=r"(a) : "l"(p));
    return a;
}

__device__ __forceinline__ void cp_async16(uint32_t dst, const void* src) {
    asm volatile("cp.async.cg.shared.global [%0], [%1], 16;"
                 :: "r"(dst), "l"(src) : "memory");
}
__device__ __forceinline__ void cp_async_commit() {
    asm volatile("cp.async.commit_group;" ::: "memory");
}
template <int N>
__device__ __forceinline__ void cp_async_wait() {
    asm volatile("cp.async.wait_group %0;" :: "n"(N) : "memory");
}

__device__ __forceinline__ void sts128(uint32_t addr, uint32_t a, uint32_t b,
                                       uint32_t c, uint32_t d) {
    asm volatile("st.shared.v4.b32 [%0], {%1,%2,%3,%4};"
                 :: "r"(addr), "r"(a), "r"(b), "r"(c), "r"(d) : "memory");
}

// ldmatrix x4: four 8x8 b16 matrices, per-lane row addresses
__device__ __forceinline__ void ldsm_x4(uint32_t& r0, uint32_t& r1,
                                        uint32_t& r2, uint32_t& r3, uint32_t addr) {
    asm volatile("ldmatrix.sync.aligned.m8n8.x4.shared.b16 {%0,%1,%2,%3}, [%4];"
                 : "=r"(r0), "=r"(r1), "=r"(r2), "=r"(r3) : "r"(addr));
}

// fp16 HMMA with fp32 accumulation: D = A(16x16) * B(16x8)^T + D
__device__ __forceinline__ void mma_f16(float* c, const uint32_t* a, const uint32_t* b) {
    asm volatile(
        "mma.sync.aligned.m16n8k16.row.col.f32.f16.f16.f32 "
        "{%0,%1,%2,%3}, {%4,%5,%6,%7}, {%8,%9}, {%0,%1,%2,%3};"
        : "+f"(c[0]), "+f"(c[1]), "+f"(c[2]), "+f"(c[3])
        : "r"(a[0]), "r"(a[1]), "r"(a[2]), "r"(a[3]), "r"(b[0]), "r"(b[1]));
}

// quantize two floats -> packed half2 bits (identical ops to the reference path)
__device__ __forceinline__ uint32_t qpack(float a, float b, float inv, float zp) {
    float qa = fminf(fmaxf(rintf(a * inv) + zp, -128.0f), 127.0f);
    float qb = fminf(fmaxf(rintf(b * inv) + zp, -128.0f), 127.0f);
    __half2 h = __floats2half2_rn(qa, qb);   // integral values: exact
    return *(uint32_t*)&h;
}

// ============================================================
// Kernel 1: per-block min/max partials over x  (+ dtype probe in block 0)
// ============================================================
__global__ void __launch_bounds__(256) k_minmax(const float4* __restrict__ x, int n4,
                                                const int* __restrict__ w) {
    __shared__ float smin[256], smax[256];
    int tid = threadIdx.x;

    if (blockIdx.x == 0) {          // dtype probe (4096 words, misclassify p ~ 2^-24/word)
        __shared__ int s_i32_ok, s_f32_ok;
        if (tid == 0) { s_i32_ok = 1; s_f32_ok = 1; }
        __syncthreads();
        int i32_ok = 1, f32_ok = 1;
        for (int i = tid; i < 4096; i += 256) {
            int v = w[i];
            if (v < -128 || v > 127) i32_ok = 0;
            float f = __int_as_float(v);
            if (!(f >= -128.0f && f <= 127.0f && rintf(f) == f)) f32_ok = 0;
        }
        if (!i32_ok) atomicAnd(&s_i32_ok, 0);
        if (!f32_ok) atomicAnd(&s_f32_ok, 0);
        __syncthreads();
        if (tid == 0) g_w_mode = s_i32_ok ? 1 : (s_f32_ok ? 2 : 0);
    }

    float mn = 0.0f, mx = 0.0f;  // min(.,0)/max(.,0) clamp folded in
    for (int i = blockIdx.x * 256 + tid; i < n4; i += 2048 * 256) {
        float4 v = x[i];
        mn = fminf(mn, fminf(fminf(v.x, v.y), fminf(v.z, v.w)));
        mx = fmaxf(mx, fmaxf(fmaxf(v.x, v.y), fmaxf(v.z, v.w)));
    }
    smin[tid] = mn; smax[tid] = mx;
    __syncthreads();
    for (int off = 128; off > 0; off >>= 1) {
        if (tid < off) {
            smin[tid] = fminf(smin[tid], smin[tid + off]);
            smax[tid] = fmaxf(smax[tid], smax[tid + off]);
        }
        __syncthreads();
    }
    if (tid == 0) { g_pmin[blockIdx.x] = smin[0]; g_pmax[blockIdx.x] = smax[0]; }
}

// ============================================================
// Kernel 2: transpose w [K,N] -> g_wth [N,K] as fp16 (dtype-agnostic read)
// ============================================================
__global__ void __launch_bounds__(256) k_transpose(const void* __restrict__ wraw) {
    __shared__ signed char t[32][33];
    const signed char* w8  = (const signed char*)wraw;
    const int*         w32 = (const int*)wraw;
    const float*       wf  = (const float*)wraw;
    int mode = g_w_mode;
    int tx = threadIdx.x, ty = threadIdx.y;
    int n0 = blockIdx.x * 32, k0 = blockIdx.y * 32;
    #pragma unroll
    for (int i = ty; i < 32; i += 8) {
        size_t idx = (size_t)(k0 + i) * NDIM + n0 + tx;
        signed char v;
        if (mode == 1)      v = (signed char)w32[idx];
        else if (mode == 2) v = (signed char)(int)wf[idx];
        else                v = w8[idx];
        t[i][tx] = v;
    }
    __syncthreads();
    #pragma unroll
    for (int i = ty; i < 32; i += 8)
        g_wth[(size_t)(n0 + i) * KDIM + k0 + tx] = __int2half_rn((int)t[tx][i]);
}

// ============================================================
// Kernel 3 (fused): scalar-reduce + on-the-fly A quantization + fp16 HMMA GEMM
//   CTA 128x256, warp tile 64x64 (2Mx4N warps), ldmatrix.x4, cp.async B pipeline.
//   A tiles: LDG f32 x -> quantize in regs -> STS fp16 (no xq buffer, no quant pass).
// ============================================================
__device__ __forceinline__ void load_B(uint32_t sb, int s, int n0, int k0e) {
    uint32_t base = sb + SM_TILES + s * STAGE_BYTES + A_STG;
    int t = threadIdx.x;
    #pragma unroll
    for (int h = 0; h < 4; ++h) {                  // B: 256 rows x 4 chunks
        int cc = t + h * 256;
        int row = cc >> 2, kw = cc & 3;
        cp_async16(base + row * ROWB + kw * 16,
                   g_wth + (size_t)(n0 + row) * KDIM + k0e + kw * 8);
    }
}

__global__ void __launch_bounds__(THREADS, 1) gemm_k(
    const float* __restrict__ x, const float* __restrict__ wsc,
    const int* __restrict__ sums, const float* __restrict__ bias,
    float* __restrict__ out)
{
    extern __shared__ char smem[];
    uint32_t sb = smem_u32(smem);
    int tid = threadIdx.x, wid = tid >> 5, lane = tid & 31;
    int warpM = wid >> 2;             // 0..1  (64 rows each)
    int warpN = wid & 3;              // 0..3  (64 cols each)
    int ntile = blockIdx.x & 3;       // consecutive bids share x rows (L2 reuse)
    int mtile = blockIdx.x >> 2;
    int m0 = mtile * BM, n0 = ntile * BN;

    // ---- per-CTA scalar reduction (replaces k_scalars; all CTAs identical) ----
    float* rmin = (float*)(smem + SM_TILES);          // scratch, overwritten by stage 0 later
    float* rmax = (float*)(smem + SM_TILES + 1024);
    {
        float mn = 0.0f, mx = 0.0f;
        #pragma unroll
        for (int j = 0; j < 8; ++j) {
            int i = tid + j * 256;
            mn = fminf(mn, g_pmin[i]);
            mx = fmaxf(mx, g_pmax[i]);
        }
        rmin[tid] = mn; rmax[tid] = mx;
        __syncthreads();
        for (int off = 128; off > 0; off >>= 1) {
            if (tid < off) {
                rmin[tid] = fminf(rmin[tid], rmin[tid + off]);
                rmax[tid] = fmaxf(rmax[tid], rmax[tid + off]);
            }
            __syncthreads();
        }
    }
    float scale = fmaxf((rmax[0] - rmin[0]) / 255.0f, EPSV);
    float zp    = fminf(fmaxf(-128.0f - rintf(rmin[0] / scale), -128.0f), 127.0f);
    float inv   = 1.0f / scale;
    __syncthreads();   // everyone has read rmin/rmax[0] before scratch is overwritten

    // epilogue coefficients (one column per thread; BN == THREADS)
    float* aS = (float*)(smem + SM_ALPHA);
    float* bS = (float*)(smem + SM_BETA);
    {
        float al = scale * wsc[n0 + tid];
        aS[tid] = al;
        bS[tid] = fmaf(-al * zp, (float)sums[n0 + tid], bias[n0 + tid]);
    }

    // A fill geometry: 256 threads; thread -> (row = tid>>1, half-row = tid&1) = 16 f32
    const float* xrow = x + (size_t)(m0 + (tid >> 1)) * KDIM + (tid & 1) * 16;
    uint32_t a_sts = sb + SM_TILES + (uint32_t)(tid >> 1) * ROWB + (uint32_t)(tid & 1) * 32;

    // ---- prologue: fill STAGES-1 stages ----
    #pragma unroll
    for (int st = 0; st < STAGES - 1; ++st) {
        const float4* src = (const float4*)(xrow + st * BKE);
        float4 v0 = src[0], v1 = src[1], v2 = src[2], v3 = src[3];
        uint32_t d = a_sts + st * STAGE_BYTES;
        sts128(d, qpack(v0.x, v0.y, inv, zp), qpack(v0.z, v0.w, inv, zp),
                  qpack(v1.x, v1.y, inv, zp), qpack(v1.z, v1.w, inv, zp));
        sts128(d + 16, qpack(v2.x, v2.y, inv, zp), qpack(v2.z, v2.w, inv, zp),
                       qpack(v3.x, v3.y, inv, zp), qpack(v3.z, v3.w, inv, zp));
        load_B(sb, st, n0, st * BKE);
        cp_async_commit();
    }

    float acc[4][8][4];
    #pragma unroll
    for (int mt = 0; mt < 4; ++mt)
        #pragma unroll
        for (int nt = 0; nt < 8; ++nt)
            #pragma unroll
            for (int r = 0; r < 4; ++r)
                acc[mt][nt][r] = 0.0f;

    int g = lane >> 2;                 // groupID 0..7
    int q = lane & 3;                  // threadID_in_group 0..3
    int sub = lane >> 3, rr = lane & 7;
    uint32_t aoff = (uint32_t)(((sub & 1) * 8 + rr) * ROWB + (sub >> 1) * 16);
    uint32_t boff = (uint32_t)(((sub >> 1) * 8 + rr) * ROWB + (sub & 1) * 16);

    for (int it = 0; it < KITERS; ++it) {
        cp_async_wait<STAGES - 2>();
        __syncthreads();

        int nx = it + STAGES - 1;
        bool fill = (nx < KITERS);
        float4 v0, v1, v2, v3;
        if (fill) {
            // issue LDGs now; consumed after compute so DRAM latency hides under MMAs
            const float4* src = (const float4*)(xrow + nx * BKE);
            v0 = src[0]; v1 = src[1]; v2 = src[2]; v3 = src[3];
            load_B(sb, nx & (STAGES - 1), n0, nx * BKE);
        }
        cp_async_commit();   // uniform group counting (possibly empty)

        int s = it & (STAGES - 1);
        uint32_t a_base = sb + SM_TILES + s * STAGE_BYTES + (warpM * 64) * ROWB + aoff;
        uint32_t b_base = sb + SM_TILES + s * STAGE_BYTES + A_STG + (warpN * 64) * ROWB + boff;

        #pragma unroll
        for (int kk = 0; kk < 2; ++kk) {       // two k16 slabs per BKE=32
            uint32_t bfr[8][2];
            #pragma unroll
            for (int nt2 = 0; nt2 < 4; ++nt2)  // each x4 covers two n8 tiles
                ldsm_x4(bfr[2 * nt2][0], bfr[2 * nt2][1],
                        bfr[2 * nt2 + 1][0], bfr[2 * nt2 + 1][1],
                        b_base + nt2 * 16 * ROWB + kk * 32);
            #pragma unroll
            for (int mt = 0; mt < 4; ++mt) {
                uint32_t af[4];
                ldsm_x4(af[0], af[1], af[2], af[3],
                        a_base + mt * 16 * ROWB + kk * 32);
                #pragma unroll
                for (int nt = 0; nt < 8; ++nt)
                    mma_f16(acc[mt][nt], af, bfr[nt]);
            }
        }

        if (fill) {
            uint32_t d = a_sts + (nx & (STAGES - 1)) * STAGE_BYTES;
            sts128(d, qpack(v0.x, v0.y, inv, zp), qpack(v0.z, v0.w, inv, zp),
                      qpack(v1.x, v1.y, inv, zp), qpack(v1.z, v1.w, inv, zp));
            sts128(d + 16, qpack(v2.x, v2.y, inv, zp), qpack(v2.z, v2.w, inv, zp),
                           qpack(v3.x, v3.y, inv, zp), qpack(v3.z, v3.w, inv, zp));
        }
    }

    // ---- epilogue: y = alpha[n]*acc + beta[n] ----
    #pragma unroll
    for (int mt = 0; mt < 4; ++mt) {
        int r0 = m0 + warpM * 64 + mt * 16 + g;
        float* out0 = out + (size_t)r0 * NDIM;
        float* out1 = out0 + (size_t)8 * NDIM;
        #pragma unroll
        for (int nt = 0; nt < 8; ++nt) {
            int cco = warpN * 64 + nt * 8 + q * 2;   // col within block
            int col = n0 + cco;
            float a0 = aS[cco], a1 = aS[cco + 1];
            float b0 = bS[cco], b1 = bS[cco + 1];
            float2 w0, w1;
            w0.x = fmaf(acc[mt][nt][0], a0, b0);
            w0.y = fmaf(acc[mt][nt][1], a1, b1);
            w1.x = fmaf(acc[mt][nt][2], a0, b0);
            w1.y = fmaf(acc[mt][nt][3], a1, b1);
            *(float2*)(out0 + col) = w0;
            *(float2*)(out1 + col) = w1;
        }
    }
}

// ============================================================
// Host launch
// ============================================================
extern "C" void kernel_launch(void* const* d_in, const int* in_sizes, int n_in,
                              void* d_out, int out_size) {
    const float* x    = (const float*)d_in[0];
    const void*  w    = d_in[1];
    const float* wsc  = (const float*)d_in[2];
    const int*   sums = (const int*)d_in[3];
    const float* bias = (const float*)d_in[4];
    float*       out  = (float*)d_out;

    cudaFuncSetAttribute(gemm_k, cudaFuncAttributeMaxDynamicSharedMemorySize,
                         SMEM_TOTAL);

    int n4 = (MDIM * KDIM) / 4;
    k_minmax<<<2048, 256>>>((const float4*)x, n4, (const int*)w);
    k_transpose<<<dim3(NDIM / 32, KDIM / 32), dim3(32, 8)>>>(w);
    gemm_k<<<(MDIM / BM) * (NDIM / BN), THREADS, SMEM_TOTAL>>>(x, wsc, sums, bias, out);
}